// round 6
// baseline (speedup 1.0000x reference)
#include <cuda_runtime.h>
#include <cuda_bf16.h>
#include <cuda_fp16.h>
#include <cstdint>

#define D 128
#define EPS 1e-5f
#define MAXN 100000
#define MAXE 1600000
#define SA 136              // padded row stride (bf16 elems) for smem tiles
#define SA_W (SA / 2)       // 68 words

// ---------------- scratch (no cudaMalloc allowed) ----------------
__device__ __half g_Z[12800000];       // N x D fp16 (GEMM out / SpMM in)
__device__ float  g_A[12800000];       // N x D fp32 (SpMM out / BN+GEMM in)
__device__ float g_stats[2 * D];       // sum[0:128], sumsq[128:256]
__device__ int   g_ticket;
__device__ float g_scale[D];
__device__ float g_shift[D];
__device__ int   g_deg[MAXN];
__device__ int   g_rowptr[MAXN + 1];
__device__ int   g_cursor[MAXN];
__device__ int   g_ecol[MAXE];
__device__ float g_ew2[MAXE];
// padded W^T bf16 hi/lo images: 3 layers x [128][136]
__device__ __nv_bfloat16 g_Whi[3 * 128 * SA];
__device__ __nv_bfloat16 g_Wlo[3 * 128 * SA];

// ---------------- prep: W transpose/split + zero deg/stats/ticket ----------------
__global__ void prep_kernel(const float* __restrict__ W0, const float* __restrict__ W1,
                            const float* __restrict__ W2,
                            __nv_bfloat16* __restrict__ whi, __nv_bfloat16* __restrict__ wlo,
                            int* __restrict__ deg, float* __restrict__ stats,
                            int* __restrict__ ticket, int N)
{
    int b = blockIdx.x;
    if (b < 3) {
        const float* W = (b == 0) ? W0 : (b == 1) ? W1 : W2;
        __nv_bfloat16* hi = whi + b * 128 * SA;
        __nv_bfloat16* lo = wlo + b * 128 * SA;
        for (int idx = threadIdx.x; idx < 16384; idx += blockDim.x) {
            int k = idx >> 7, n = idx & 127;     // W[k][n] -> Wt[n][k]
            float w = W[idx];
            __nv_bfloat16 h = __float2bfloat16(w);
            __nv_bfloat16 l = __float2bfloat16(w - __bfloat162float(h));
            hi[n * SA + k] = h;
            lo[n * SA + k] = l;
        }
    } else if (b == 3) {
        if (threadIdx.x < 2 * D) stats[threadIdx.x] = 0.f;
        if (threadIdx.x == 0) *ticket = 0;
    } else {
        // blocks 4..15 zero deg
        int per = (N + 11) / 12;
        int beg = (b - 4) * per;
        int end = min(beg + per, N);
        for (int i = beg + (int)threadIdx.x; i < end; i += blockDim.x) deg[i] = 0;
    }
}

// ---------------- HMMA GEMM: Z(fp16) = act(H) @ W + b   (bf16x3, fp32 acc) ----------------
#define SM_AHI 0
#define SM_ALO 17408
#define SM_WHI 34816
#define SM_WLO 69632
#define SM_TOT 104448

__device__ __forceinline__ void mma_bf16(float* c, uint32_t a0, uint32_t a1,
                                         uint32_t a2, uint32_t a3,
                                         uint32_t b0, uint32_t b1)
{
    asm volatile(
        "mma.sync.aligned.m16n8k16.row.col.f32.bf16.bf16.f32 "
        "{%0,%1,%2,%3}, {%4,%5,%6,%7}, {%8,%9}, {%0,%1,%2,%3};"
        : "+f"(c[0]), "+f"(c[1]), "+f"(c[2]), "+f"(c[3])
        : "r"(a0), "r"(a1), "r"(a2), "r"(a3), "r"(b0), "r"(b1));
}

__global__ __launch_bounds__(256) void gemm_mma_kernel(
    const float* __restrict__ H,
    const __nv_bfloat16* __restrict__ whi, const __nv_bfloat16* __restrict__ wlo,
    const float* __restrict__ bias,
    const float* __restrict__ scale, const float* __restrict__ shift,
    __half* __restrict__ out, int N, int use_act)
{
    extern __shared__ char sm[];
    int tid = threadIdx.x, wid = tid >> 5, lane = tid & 31;

    // stage W hi/lo (straight copy, already padded/transposed): 2176 float4 each
    {
        const float4* bh = (const float4*)whi;
        const float4* bl = (const float4*)wlo;
        float4* sh = (float4*)(sm + SM_WHI);
        float4* sl = (float4*)(sm + SM_WLO);
#pragma unroll
        for (int i = 0; i < 9; i++) {
            int idx = tid + 256 * i;
            if (idx < 2176) { sh[idx] = bh[idx]; sl[idx] = bl[idx]; }
        }
    }

    // stage A tile: load H rows, act, bf16 split, padded store
    int row0 = blockIdx.x * 64;
    {
        const float4* Hv = (const float4*)(H + (size_t)row0 * D);
#pragma unroll
        for (int i = 0; i < 8; i++) {
            int idx = tid + 256 * i;          // 2048 float4
            int r = idx >> 5;
            int c = (idx & 31) * 4;
            float4 v;
            if (row0 + r < N) v = Hv[idx];
            else              v = make_float4(0.f, 0.f, 0.f, 0.f);
            if (use_act) {
                float4 sc = *(const float4*)(scale + c);
                float4 sf = *(const float4*)(shift + c);
                v.x = fmaxf(fmaf(v.x, sc.x, sf.x), 0.f);
                v.y = fmaxf(fmaf(v.y, sc.y, sf.y), 0.f);
                v.z = fmaxf(fmaf(v.z, sc.z, sf.z), 0.f);
                v.w = fmaxf(fmaf(v.w, sc.w, sf.w), 0.f);
            }
            __nv_bfloat162 h01 = __floats2bfloat162_rn(v.x, v.y);
            __nv_bfloat162 h23 = __floats2bfloat162_rn(v.z, v.w);
            float2 hf01 = __bfloat1622float2(h01);
            float2 hf23 = __bfloat1622float2(h23);
            __nv_bfloat162 l01 = __floats2bfloat162_rn(v.x - hf01.x, v.y - hf01.y);
            __nv_bfloat162 l23 = __floats2bfloat162_rn(v.z - hf23.x, v.w - hf23.y);
            uint32_t w0 = (uint32_t)(r * SA_W + (c >> 1));   // word index, 8B aligned
            uint2 hh; hh.x = *(uint32_t*)&h01; hh.y = *(uint32_t*)&h23;
            uint2 ll; ll.x = *(uint32_t*)&l01; ll.y = *(uint32_t*)&l23;
            *(uint2*)(sm + SM_AHI + w0 * 4) = hh;
            *(uint2*)(sm + SM_ALO + w0 * 4) = ll;
        }
    }
    __syncthreads();

    const uint32_t* pAh = (const uint32_t*)(sm + SM_AHI);
    const uint32_t* pAl = (const uint32_t*)(sm + SM_ALO);
    const uint32_t* pBh = (const uint32_t*)(sm + SM_WHI);
    const uint32_t* pBl = (const uint32_t*)(sm + SM_WLO);

    int m0 = (wid & 3) * 16;      // row strip
    int n0 = (wid >> 2) * 64;     // col half
    int g = lane >> 2, q = lane & 3;

    float acc[8][4] = {};
#pragma unroll
    for (int k = 0; k < 8; k++) {
        int kb2 = k * 8;          // k*16 elems = 8 words
        int ai = (m0 + g) * SA_W + kb2 + q;
        uint32_t ah0 = pAh[ai],           ah1 = pAh[ai + 8 * SA_W];
        uint32_t ah2 = pAh[ai + 4],       ah3 = pAh[ai + 8 * SA_W + 4];
        uint32_t al0 = pAl[ai],           al1 = pAl[ai + 8 * SA_W];
        uint32_t al2 = pAl[ai + 4],       al3 = pAl[ai + 8 * SA_W + 4];
#pragma unroll
        for (int t = 0; t < 8; t++) {
            int bi = (n0 + t * 8 + g) * SA_W + kb2 + q;
            uint32_t bh0 = pBh[bi], bh1 = pBh[bi + 4];
            uint32_t bl0 = pBl[bi], bl1 = pBl[bi + 4];
            mma_bf16(acc[t], ah0, ah1, ah2, ah3, bh0, bh1);
            mma_bf16(acc[t], al0, al1, al2, al3, bh0, bh1);
            mma_bf16(acc[t], ah0, ah1, ah2, ah3, bl0, bl1);
        }
    }

    // epilogue: write fp16; c0,c1 -> row m0+g ; c2,c3 -> row m0+g+8
    int r0g = row0 + m0 + g;
#pragma unroll
    for (int t = 0; t < 8; t++) {
        int colp = n0 + t * 8 + q * 2;
        float2 bv = *(const float2*)(bias + colp);
        if (r0g < N) {
            __half2 o = __floats2half2_rn(acc[t][0] + bv.x, acc[t][1] + bv.y);
            *(__half2*)(out + (size_t)r0g * D + colp) = o;
        }
        if (r0g + 8 < N) {
            __half2 o = __floats2half2_rn(acc[t][2] + bv.x, acc[t][3] + bv.y);
            *(__half2*)(out + (size_t)(r0g + 8) * D + colp) = o;
        }
    }
}

// ---------------- CSR build ----------------
__global__ void hist_kernel(const int* __restrict__ row, int* __restrict__ deg, int E)
{
    int e = blockIdx.x * blockDim.x + threadIdx.x;
    if (e < E) atomicAdd(&deg[row[e]], 1);
}

// single-block tiled inclusive->exclusive scan; writes rowptr AND cursor
__global__ __launch_bounds__(1024) void csr_scan_kernel(
    const int* __restrict__ deg, int* __restrict__ rowptr,
    int* __restrict__ cursor, int N)
{
    __shared__ int wsum[32];
    __shared__ int carry;
    int tid = threadIdx.x, lane = tid & 31, wid = tid >> 5;
    if (tid == 0) carry = 0;
    __syncthreads();
    for (int base = 0; base < N; base += 1024) {
        int i = base + tid;
        int v = (i < N) ? deg[i] : 0;
        int incl = v;
#pragma unroll
        for (int off = 1; off < 32; off <<= 1) {
            int t = __shfl_up_sync(0xffffffffu, incl, off);
            if (lane >= off) incl += t;
        }
        if (lane == 31) wsum[wid] = incl;
        __syncthreads();
        if (wid == 0) {
            int w = wsum[lane];
#pragma unroll
            for (int off = 1; off < 32; off <<= 1) {
                int t = __shfl_up_sync(0xffffffffu, w, off);
                if (lane >= off) w += t;
            }
            wsum[lane] = w;
        }
        __syncthreads();
        int excl = carry + incl - v + (wid > 0 ? wsum[wid - 1] : 0);
        if (i < N) { rowptr[i] = excl; cursor[i] = excl; }
        if (i == N - 1) rowptr[N] = excl + v;
        __syncthreads();
        if (tid == 0) carry += wsum[31];
        __syncthreads();
    }
}

__global__ void scatter_kernel(
    const int* __restrict__ row, const int* __restrict__ col,
    const float* __restrict__ ew, int* __restrict__ cursor,
    int* __restrict__ ecol, float* __restrict__ ew2, int E)
{
    int e = blockIdx.x * blockDim.x + threadIdx.x;
    if (e < E) {
        int p = atomicAdd(&cursor[row[e]], 1);
        ecol[p] = col[e];
        ew2[p]  = ew[e];
    }
}

// ---------------- fused gather SpMM + BN stats + finalize ----------------
// one warp per row; block = 8 rows. do_bn: block-reduce column sums,
// global atomics, last block computes scale/shift and resets stats/ticket.
__global__ __launch_bounds__(256) void spmm_bn_kernel(
    const __half* __restrict__ H, const int* __restrict__ rowptr,
    const int* __restrict__ ecol, const float* __restrict__ ew2,
    float* __restrict__ out,
    float* __restrict__ stats, int* __restrict__ ticket,
    const float* __restrict__ g, const float* __restrict__ be,
    float* __restrict__ scale, float* __restrict__ shift,
    int N, int do_bn, float invN)
{
    int tid = threadIdx.x, wid = tid >> 5, lane = tid & 31;
    int r = blockIdx.x * 8 + wid;

    float4 acc = make_float4(0.f, 0.f, 0.f, 0.f);
    if (r < N) {
        int start = rowptr[r], end = rowptr[r + 1];
        const uint2* Hv = (const uint2*)H;
        for (int base = start; base < end; base += 32) {
            int e = base + lane;
            int c = 0; float w = 0.f;
            if (e < end) { c = ecol[e]; w = ew2[e]; }
            int cnt = min(32, end - base);
#pragma unroll 4
            for (int i = 0; i < cnt; i++) {
                int ci  = __shfl_sync(0xffffffffu, c, i);
                float wi = __shfl_sync(0xffffffffu, w, i);
                uint2 pv = Hv[(size_t)ci * 32 + lane];
                float2 v01 = __half22float2(*(__half2*)&pv.x);
                float2 v23 = __half22float2(*(__half2*)&pv.y);
                acc.x = fmaf(wi, v01.x, acc.x);
                acc.y = fmaf(wi, v01.y, acc.y);
                acc.z = fmaf(wi, v23.x, acc.z);
                acc.w = fmaf(wi, v23.y, acc.w);
            }
        }
        ((float4*)(out + (size_t)r * D))[lane] = acc;
    }

    if (!do_bn) return;

    __shared__ float red[8][128];
    __shared__ int is_last;
    *(float4*)&red[wid][lane * 4] = acc;   // zeros for r >= N
    __syncthreads();

    if (tid < 128) {
        float s = 0.f, q = 0.f;
#pragma unroll
        for (int w = 0; w < 8; w++) {
            float v = red[w][tid];
            s += v;
            q = fmaf(v, v, q);
        }
        atomicAdd(&stats[tid], s);
        atomicAdd(&stats[128 + tid], q);
    }
    __threadfence();
    __syncthreads();
    if (tid == 0) is_last = (atomicAdd(ticket, 1) == (int)gridDim.x - 1);
    __syncthreads();

    if (is_last) {
        if (tid < 128) {
            float m = __ldcg(&stats[tid]) * invN;
            float v = __ldcg(&stats[128 + tid]) * invN - m * m;
            float sc = g[tid] * rsqrtf(v + EPS);
            scale[tid] = sc;
            shift[tid] = be[tid] - m * sc;
        }
        __syncthreads();
        if (tid < 128) { stats[tid] = 0.f; stats[128 + tid] = 0.f; }
        if (tid == 0) *ticket = 0;
    }
}

// ---------------------------------------------------------------------------
extern "C" void kernel_launch(void* const* d_in, const int* in_sizes, int n_in,
                              void* d_out, int out_size)
{
    const float* x   = (const float*)d_in[0];
    const float* ew  = (const float*)d_in[1];
    const float* W0  = (const float*)d_in[2];
    const float* b0  = (const float*)d_in[3];
    const float* g0  = (const float*)d_in[4];
    const float* be0 = (const float*)d_in[5];
    const float* W1  = (const float*)d_in[6];
    const float* b1  = (const float*)d_in[7];
    const float* g1  = (const float*)d_in[8];
    const float* be1 = (const float*)d_in[9];
    const float* W2  = (const float*)d_in[10];
    const float* b2  = (const float*)d_in[11];
    const int*   row = (const int*)d_in[12];
    const int*   col = (const int*)d_in[13];
    float* out = (float*)d_out;

    int N = in_sizes[0] / D;
    int E = in_sizes[1];

    float *A, *Stats, *Scale, *Shift, *Ew2;
    __half* Z;
    int *Deg, *Rowptr, *Cursor, *Ecol, *Ticket;
    __nv_bfloat16 *Whi, *Wlo;
    cudaGetSymbolAddress((void**)&Z, g_Z);
    cudaGetSymbolAddress((void**)&A, g_A);
    cudaGetSymbolAddress((void**)&Stats, g_stats);
    cudaGetSymbolAddress((void**)&Ticket, g_ticket);
    cudaGetSymbolAddress((void**)&Scale, g_scale);
    cudaGetSymbolAddress((void**)&Shift, g_shift);
    cudaGetSymbolAddress((void**)&Deg, g_deg);
    cudaGetSymbolAddress((void**)&Rowptr, g_rowptr);
    cudaGetSymbolAddress((void**)&Cursor, g_cursor);
    cudaGetSymbolAddress((void**)&Ecol, g_ecol);
    cudaGetSymbolAddress((void**)&Ew2, g_ew2);
    cudaGetSymbolAddress((void**)&Whi, g_Whi);
    cudaGetSymbolAddress((void**)&Wlo, g_Wlo);

    cudaFuncSetAttribute(gemm_mma_kernel, cudaFuncAttributeMaxDynamicSharedMemorySize, SM_TOT);

    int gemmGrid = (N + 63) / 64;
    int spmmGrid = (N + 7) / 8;
    float invN = 1.0f / (float)N;

    // ---- prep (W images + zero deg/stats/ticket) + CSR build ----
    prep_kernel<<<16, 256>>>(W0, W1, W2, Whi, Wlo, Deg, Stats, Ticket, N);
    hist_kernel<<<(E + 255) / 256, 256>>>(row, Deg, E);
    csr_scan_kernel<<<1, 1024>>>(Deg, Rowptr, Cursor, N);
    scatter_kernel<<<(E + 255) / 256, 256>>>(row, col, ew, Cursor, Ecol, Ew2, E);

    // ---- layer 0 ----
    gemm_mma_kernel<<<gemmGrid, 256, SM_TOT>>>(x, Whi, Wlo, b0, nullptr, nullptr, Z, N, 0);
    spmm_bn_kernel<<<spmmGrid, 256>>>(Z, Rowptr, Ecol, Ew2, A, Stats, Ticket,
                                      g0, be0, Scale, Shift, N, 1, invN);

    // ---- layer 1 ----
    gemm_mma_kernel<<<gemmGrid, 256, SM_TOT>>>(A, Whi + 128 * SA, Wlo + 128 * SA, b1,
                                               Scale, Shift, Z, N, 1);
    spmm_bn_kernel<<<spmmGrid, 256>>>(Z, Rowptr, Ecol, Ew2, A, Stats, Ticket,
                                      g1, be1, Scale, Shift, N, 1, invN);

    // ---- layer 2 (no BN) ----
    gemm_mma_kernel<<<gemmGrid, 256, SM_TOT>>>(A, Whi + 256 * SA, Wlo + 256 * SA, b2,
                                               Scale, Shift, Z, N, 1);
    spmm_bn_kernel<<<spmmGrid, 256>>>(Z, Rowptr, Ecol, Ew2, out, Stats, Ticket,
                                      nullptr, nullptr, nullptr, nullptr, N, 0, invN);
}

// round 7
// speedup vs baseline: 1.1428x; 1.1428x over previous
#include <cuda_runtime.h>
#include <cuda_bf16.h>
#include <cuda_fp16.h>
#include <cstdint>

#define D 128
#define EPS 1e-5f
#define MAXN 100000
#define MAXE 1600000
#define SA 136              // padded row stride (bf16 elems) for smem tiles
#define SA_W (SA / 2)       // 68 words

// ---------------- scratch (no cudaMalloc allowed) ----------------
__device__ __half g_Z[12800000];       // N x D fp16 (GEMM out / SpMM in)
__device__ float  g_A[12800000];       // N x D fp32 (SpMM out / BN+GEMM in)
__device__ float g_stats[2 * D];       // sum[0:128], sumsq[128:256]
__device__ float g_scale[D];
__device__ float g_shift[D];
__device__ int   g_deg[MAXN];
__device__ int   g_rowptr[MAXN + 1];
__device__ int   g_cursor[MAXN];
__device__ int   g_ecol[MAXE];
__device__ float g_ew2[MAXE];
__device__ int   g_blksum[1024];
// padded W^T bf16 hi/lo images: 3 layers x [128][136]
__device__ __nv_bfloat16 g_Whi[3 * 128 * SA];
__device__ __nv_bfloat16 g_Wlo[3 * 128 * SA];

// ---------------- prep: W transpose/split + zero deg/stats ----------------
__global__ void prep_kernel(const float* __restrict__ W0, const float* __restrict__ W1,
                            const float* __restrict__ W2,
                            __nv_bfloat16* __restrict__ whi, __nv_bfloat16* __restrict__ wlo,
                            int* __restrict__ deg, float* __restrict__ stats, int N)
{
    int b = blockIdx.x;
    if (b < 3) {
        const float* W = (b == 0) ? W0 : (b == 1) ? W1 : W2;
        __nv_bfloat16* hi = whi + b * 128 * SA;
        __nv_bfloat16* lo = wlo + b * 128 * SA;
        for (int idx = threadIdx.x; idx < 16384; idx += blockDim.x) {
            int k = idx >> 7, n = idx & 127;     // W[k][n] -> Wt[n][k]
            float w = W[idx];
            __nv_bfloat16 h = __float2bfloat16(w);
            __nv_bfloat16 l = __float2bfloat16(w - __bfloat162float(h));
            hi[n * SA + k] = h;
            lo[n * SA + k] = l;
        }
    } else if (b == 3) {
        if (threadIdx.x < 2 * D) stats[threadIdx.x] = 0.f;
    } else {
        // blocks 4..15 zero deg
        int per = (N + 11) / 12;
        int beg = (b - 4) * per;
        int end = min(beg + per, N);
        for (int i = beg + (int)threadIdx.x; i < end; i += blockDim.x) deg[i] = 0;
    }
}

// ---------------- HMMA GEMM: Z(fp16) = act(H) @ W + b   (bf16x3, fp32 acc) ----------------
#define SM_AHI 0
#define SM_ALO 17408
#define SM_WHI 34816
#define SM_WLO 69632
#define SM_TOT 104448

__device__ __forceinline__ void mma_bf16(float* c, uint32_t a0, uint32_t a1,
                                         uint32_t a2, uint32_t a3,
                                         uint32_t b0, uint32_t b1)
{
    asm volatile(
        "mma.sync.aligned.m16n8k16.row.col.f32.bf16.bf16.f32 "
        "{%0,%1,%2,%3}, {%4,%5,%6,%7}, {%8,%9}, {%0,%1,%2,%3};"
        : "+f"(c[0]), "+f"(c[1]), "+f"(c[2]), "+f"(c[3])
        : "r"(a0), "r"(a1), "r"(a2), "r"(a3), "r"(b0), "r"(b1));
}

__global__ __launch_bounds__(256) void gemm_mma_kernel(
    const float* __restrict__ H,
    const __nv_bfloat16* __restrict__ whi, const __nv_bfloat16* __restrict__ wlo,
    const float* __restrict__ bias,
    const float* __restrict__ scale, const float* __restrict__ shift,
    __half* __restrict__ out, int N, int use_act)
{
    extern __shared__ char sm[];
    int tid = threadIdx.x, wid = tid >> 5, lane = tid & 31;

    // stage W hi/lo (straight copy, already padded/transposed): 2176 float4 each
    {
        const float4* bh = (const float4*)whi;
        const float4* bl = (const float4*)wlo;
        float4* sh = (float4*)(sm + SM_WHI);
        float4* sl = (float4*)(sm + SM_WLO);
#pragma unroll
        for (int i = 0; i < 9; i++) {
            int idx = tid + 256 * i;
            if (idx < 2176) { sh[idx] = bh[idx]; sl[idx] = bl[idx]; }
        }
    }

    // stage A tile: load H rows, act, bf16 split, padded store
    int row0 = blockIdx.x * 64;
    {
        const float4* Hv = (const float4*)(H + (size_t)row0 * D);
#pragma unroll
        for (int i = 0; i < 8; i++) {
            int idx = tid + 256 * i;          // 2048 float4
            int r = idx >> 5;
            int c = (idx & 31) * 4;
            float4 v;
            if (row0 + r < N) v = Hv[idx];
            else              v = make_float4(0.f, 0.f, 0.f, 0.f);
            if (use_act) {
                float4 sc = *(const float4*)(scale + c);
                float4 sf = *(const float4*)(shift + c);
                v.x = fmaxf(fmaf(v.x, sc.x, sf.x), 0.f);
                v.y = fmaxf(fmaf(v.y, sc.y, sf.y), 0.f);
                v.z = fmaxf(fmaf(v.z, sc.z, sf.z), 0.f);
                v.w = fmaxf(fmaf(v.w, sc.w, sf.w), 0.f);
            }
            __nv_bfloat162 h01 = __floats2bfloat162_rn(v.x, v.y);
            __nv_bfloat162 h23 = __floats2bfloat162_rn(v.z, v.w);
            float2 hf01 = __bfloat1622float2(h01);
            float2 hf23 = __bfloat1622float2(h23);
            __nv_bfloat162 l01 = __floats2bfloat162_rn(v.x - hf01.x, v.y - hf01.y);
            __nv_bfloat162 l23 = __floats2bfloat162_rn(v.z - hf23.x, v.w - hf23.y);
            uint32_t w0 = (uint32_t)(r * SA_W + (c >> 1));   // word index, 8B aligned
            uint2 hh; hh.x = *(uint32_t*)&h01; hh.y = *(uint32_t*)&h23;
            uint2 ll; ll.x = *(uint32_t*)&l01; ll.y = *(uint32_t*)&l23;
            *(uint2*)(sm + SM_AHI + w0 * 4) = hh;
            *(uint2*)(sm + SM_ALO + w0 * 4) = ll;
        }
    }
    __syncthreads();

    const uint32_t* pAh = (const uint32_t*)(sm + SM_AHI);
    const uint32_t* pAl = (const uint32_t*)(sm + SM_ALO);
    const uint32_t* pBh = (const uint32_t*)(sm + SM_WHI);
    const uint32_t* pBl = (const uint32_t*)(sm + SM_WLO);

    int m0 = (wid & 3) * 16;      // row strip
    int n0 = (wid >> 2) * 64;     // col half
    int g = lane >> 2, q = lane & 3;

    float acc[8][4] = {};
#pragma unroll
    for (int k = 0; k < 8; k++) {
        int kb2 = k * 8;          // k*16 elems = 8 words
        int ai = (m0 + g) * SA_W + kb2 + q;
        uint32_t ah0 = pAh[ai],           ah1 = pAh[ai + 8 * SA_W];
        uint32_t ah2 = pAh[ai + 4],       ah3 = pAh[ai + 8 * SA_W + 4];
        uint32_t al0 = pAl[ai],           al1 = pAl[ai + 8 * SA_W];
        uint32_t al2 = pAl[ai + 4],       al3 = pAl[ai + 8 * SA_W + 4];
#pragma unroll
        for (int t = 0; t < 8; t++) {
            int bi = (n0 + t * 8 + g) * SA_W + kb2 + q;
            uint32_t bh0 = pBh[bi], bh1 = pBh[bi + 4];
            uint32_t bl0 = pBl[bi], bl1 = pBl[bi + 4];
            mma_bf16(acc[t], ah0, ah1, ah2, ah3, bh0, bh1);
            mma_bf16(acc[t], al0, al1, al2, al3, bh0, bh1);
            mma_bf16(acc[t], ah0, ah1, ah2, ah3, bl0, bl1);
        }
    }

    // epilogue: write fp16; c0,c1 -> row m0+g ; c2,c3 -> row m0+g+8
    int r0g = row0 + m0 + g;
#pragma unroll
    for (int t = 0; t < 8; t++) {
        int colp = n0 + t * 8 + q * 2;
        float2 bv = *(const float2*)(bias + colp);
        if (r0g < N) {
            __half2 o = __floats2half2_rn(acc[t][0] + bv.x, acc[t][1] + bv.y);
            *(__half2*)(out + (size_t)r0g * D + colp) = o;
        }
        if (r0g + 8 < N) {
            __half2 o = __floats2half2_rn(acc[t][2] + bv.x, acc[t][3] + bv.y);
            *(__half2*)(out + (size_t)(r0g + 8) * D + colp) = o;
        }
    }
}

// ---------------- CSR build ----------------
__global__ void hist_kernel(const int* __restrict__ row, int* __restrict__ deg, int E)
{
    int e = blockIdx.x * blockDim.x + threadIdx.x;
    if (e < E) atomicAdd(&deg[row[e]], 1);
}

__global__ __launch_bounds__(1024) void blocksum_kernel(
    const int* __restrict__ deg, int* __restrict__ blksum, int N)
{
    int i = blockIdx.x * 1024 + threadIdx.x;
    int v = (i < N) ? deg[i] : 0;
#pragma unroll
    for (int off = 16; off > 0; off >>= 1) v += __shfl_down_sync(0xffffffffu, v, off);
    __shared__ int smr[32];
    int lane = threadIdx.x & 31, wid = threadIdx.x >> 5;
    if (lane == 0) smr[wid] = v;
    __syncthreads();
    if (wid == 0) {
        v = smr[lane];
#pragma unroll
        for (int off = 16; off > 0; off >>= 1) v += __shfl_down_sync(0xffffffffu, v, off);
        if (lane == 0) blksum[blockIdx.x] = v;
    }
}

__global__ __launch_bounds__(1024) void scanpart_kernel(int* __restrict__ blksum, int nb)
{
    __shared__ int smr[1024];
    int tid = threadIdx.x;
    smr[tid] = (tid < nb) ? blksum[tid] : 0;
    __syncthreads();
    if (tid == 0) {
        int run = 0;
        for (int i = 0; i < nb; i++) { int t = smr[i]; smr[i] = run; run += t; }
    }
    __syncthreads();
    if (tid < nb) blksum[tid] = smr[tid];
}

// writes rowptr AND cursor (no separate memcpy)
__global__ __launch_bounds__(1024) void rowptr_kernel(
    const int* __restrict__ deg, const int* __restrict__ blksum,
    int* __restrict__ rowptr, int* __restrict__ cursor, int N)
{
    int i = blockIdx.x * 1024 + threadIdx.x;
    int v = (i < N) ? deg[i] : 0;
    int lane = threadIdx.x & 31, wid = threadIdx.x >> 5;
    int incl = v;
#pragma unroll
    for (int off = 1; off < 32; off <<= 1) {
        int t = __shfl_up_sync(0xffffffffu, incl, off);
        if (lane >= off) incl += t;
    }
    __shared__ int wsum[32];
    if (lane == 31) wsum[wid] = incl;
    __syncthreads();
    if (wid == 0) {
        int w = wsum[lane];
#pragma unroll
        for (int off = 1; off < 32; off <<= 1) {
            int t = __shfl_up_sync(0xffffffffu, w, off);
            if (lane >= off) w += t;
        }
        wsum[lane] = w;
    }
    __syncthreads();
    int offset = blksum[blockIdx.x] + (wid > 0 ? wsum[wid - 1] : 0);
    int excl = offset + incl - v;
    if (i < N) { rowptr[i] = excl; cursor[i] = excl; }
    if (i == N - 1) rowptr[N] = excl + v;
}

__global__ void scatter_kernel(
    const int* __restrict__ row, const int* __restrict__ col,
    const float* __restrict__ ew, int* __restrict__ cursor,
    int* __restrict__ ecol, float* __restrict__ ew2, int E)
{
    int e = blockIdx.x * blockDim.x + threadIdx.x;
    if (e < E) {
        int p = atomicAdd(&cursor[row[e]], 1);
        ecol[p] = col[e];
        ew2[p]  = ew[e];
    }
}

// ---------------- fused gather SpMM + BN stats (no fence, no finalize) ----------------
__global__ __launch_bounds__(256) void spmm_bn_kernel(
    const __half* __restrict__ H, const int* __restrict__ rowptr,
    const int* __restrict__ ecol, const float* __restrict__ ew2,
    float* __restrict__ out, float* __restrict__ stats,
    int N, int do_bn)
{
    int tid = threadIdx.x, wid = tid >> 5, lane = tid & 31;
    int r = blockIdx.x * 8 + wid;

    float4 acc = make_float4(0.f, 0.f, 0.f, 0.f);
    if (r < N) {
        int start = rowptr[r], end = rowptr[r + 1];
        const uint2* Hv = (const uint2*)H;
        for (int base = start; base < end; base += 32) {
            int e = base + lane;
            int c = 0; float w = 0.f;
            if (e < end) { c = ecol[e]; w = ew2[e]; }
            int cnt = min(32, end - base);
#pragma unroll 4
            for (int i = 0; i < cnt; i++) {
                int ci  = __shfl_sync(0xffffffffu, c, i);
                float wi = __shfl_sync(0xffffffffu, w, i);
                uint2 pv = Hv[(size_t)ci * 32 + lane];
                float2 v01 = __half22float2(*(__half2*)&pv.x);
                float2 v23 = __half22float2(*(__half2*)&pv.y);
                acc.x = fmaf(wi, v01.x, acc.x);
                acc.y = fmaf(wi, v01.y, acc.y);
                acc.z = fmaf(wi, v23.x, acc.z);
                acc.w = fmaf(wi, v23.y, acc.w);
            }
        }
        ((float4*)(out + (size_t)r * D))[lane] = acc;
    }

    if (!do_bn) return;

    __shared__ float red[8][128];
    *(float4*)&red[wid][lane * 4] = acc;   // zeros for r >= N
    __syncthreads();

    if (tid < 128) {
        float s = 0.f, q = 0.f;
#pragma unroll
        for (int w = 0; w < 8; w++) {
            float v = red[w][tid];
            s += v;
            q = fmaf(v, v, q);
        }
        atomicAdd(&stats[tid], s);
        atomicAdd(&stats[128 + tid], q);
    }
}

// finalize: scale/shift from stats, then reset stats for the next layer.
__global__ void bn_finalize_kernel(
    float* __restrict__ stats,
    const float* __restrict__ g, const float* __restrict__ be,
    float* __restrict__ scale, float* __restrict__ shift, float invN)
{
    int d = threadIdx.x;
    float m = stats[d] * invN;
    float v = stats[128 + d] * invN - m * m;
    float sc = g[d] * rsqrtf(v + EPS);
    scale[d] = sc;
    shift[d] = be[d] - m * sc;
    stats[d] = 0.f;
    stats[128 + d] = 0.f;
}

// ---------------------------------------------------------------------------
extern "C" void kernel_launch(void* const* d_in, const int* in_sizes, int n_in,
                              void* d_out, int out_size)
{
    const float* x   = (const float*)d_in[0];
    const float* ew  = (const float*)d_in[1];
    const float* W0  = (const float*)d_in[2];
    const float* b0  = (const float*)d_in[3];
    const float* g0  = (const float*)d_in[4];
    const float* be0 = (const float*)d_in[5];
    const float* W1  = (const float*)d_in[6];
    const float* b1  = (const float*)d_in[7];
    const float* g1  = (const float*)d_in[8];
    const float* be1 = (const float*)d_in[9];
    const float* W2  = (const float*)d_in[10];
    const float* b2  = (const float*)d_in[11];
    const int*   row = (const int*)d_in[12];
    const int*   col = (const int*)d_in[13];
    float* out = (float*)d_out;

    int N = in_sizes[0] / D;
    int E = in_sizes[1];

    float *A, *Stats, *Scale, *Shift, *Ew2;
    __half* Z;
    int *Deg, *Rowptr, *Cursor, *Ecol, *Blksum;
    __nv_bfloat16 *Whi, *Wlo;
    cudaGetSymbolAddress((void**)&Z, g_Z);
    cudaGetSymbolAddress((void**)&A, g_A);
    cudaGetSymbolAddress((void**)&Stats, g_stats);
    cudaGetSymbolAddress((void**)&Scale, g_scale);
    cudaGetSymbolAddress((void**)&Shift, g_shift);
    cudaGetSymbolAddress((void**)&Deg, g_deg);
    cudaGetSymbolAddress((void**)&Rowptr, g_rowptr);
    cudaGetSymbolAddress((void**)&Cursor, g_cursor);
    cudaGetSymbolAddress((void**)&Ecol, g_ecol);
    cudaGetSymbolAddress((void**)&Ew2, g_ew2);
    cudaGetSymbolAddress((void**)&Blksum, g_blksum);
    cudaGetSymbolAddress((void**)&Whi, g_Whi);
    cudaGetSymbolAddress((void**)&Wlo, g_Wlo);

    cudaFuncSetAttribute(gemm_mma_kernel, cudaFuncAttributeMaxDynamicSharedMemorySize, SM_TOT);

    int gemmGrid = (N + 63) / 64;
    int spmmGrid = (N + 7) / 8;
    int nb       = (N + 1023) / 1024;
    float invN = 1.0f / (float)N;

    // ---- prep (W images + zero deg/stats) + CSR build ----
    prep_kernel<<<16, 256>>>(W0, W1, W2, Whi, Wlo, Deg, Stats, N);
    hist_kernel<<<(E + 255) / 256, 256>>>(row, Deg, E);
    blocksum_kernel<<<nb, 1024>>>(Deg, Blksum, N);
    scanpart_kernel<<<1, 1024>>>(Blksum, nb);
    rowptr_kernel<<<nb, 1024>>>(Deg, Blksum, Rowptr, Cursor, N);
    scatter_kernel<<<(E + 255) / 256, 256>>>(row, col, ew, Cursor, Ecol, Ew2, E);

    // ---- layer 0 ----
    gemm_mma_kernel<<<gemmGrid, 256, SM_TOT>>>(x, Whi, Wlo, b0, nullptr, nullptr, Z, N, 0);
    spmm_bn_kernel<<<spmmGrid, 256>>>(Z, Rowptr, Ecol, Ew2, A, Stats, N, 1);
    bn_finalize_kernel<<<1, 128>>>(Stats, g0, be0, Scale, Shift, invN);

    // ---- layer 1 ----
    gemm_mma_kernel<<<gemmGrid, 256, SM_TOT>>>(A, Whi + 128 * SA, Wlo + 128 * SA, b1,
                                               Scale, Shift, Z, N, 1);
    spmm_bn_kernel<<<spmmGrid, 256>>>(Z, Rowptr, Ecol, Ew2, A, Stats, N, 1);
    bn_finalize_kernel<<<1, 128>>>(Stats, g1, be1, Scale, Shift, invN);

    // ---- layer 2 (no BN) ----
    gemm_mma_kernel<<<gemmGrid, 256, SM_TOT>>>(A, Whi + 256 * SA, Wlo + 256 * SA, b2,
                                               Scale, Shift, Z, N, 1);
    spmm_bn_kernel<<<spmmGrid, 256>>>(Z, Rowptr, Ecol, Ew2, out, Stats, N, 0);
}

// round 10
// speedup vs baseline: 1.5010x; 1.3134x over previous
#include <cuda_runtime.h>
#include <cuda_bf16.h>
#include <cuda_fp16.h>
#include <cstdint>

#define D 128
#define EPS 1e-5f
#define MAXN 100000
#define MAXE 1600000
#define SA 136
#define SA_W (SA / 2)

__device__ __half g_Z[12800000];
__device__ float  g_A[12800000];
__device__ float g_stats[4 * D];       // layer0: [0:256), layer1: [256:512)
__device__ int   g_deg[MAXN];
__device__ int   g_rowptr[MAXN + 1];
__device__ int   g_cursor[MAXN];
__device__ int2  g_edata[MAXE];
__device__ int   g_blksum[1024];
__device__ __nv_bfloat16 g_Whi[3 * 128 * SA];
__device__ __nv_bfloat16 g_Wlo[3 * 128 * SA];

// ---------------- prep: W transpose/split + zero deg + zero BOTH stats buffers ------
__global__ void prep_kernel(const float* __restrict__ W0, const float* __restrict__ W1,
                            const float* __restrict__ W2,
                            __nv_bfloat16* __restrict__ whi, __nv_bfloat16* __restrict__ wlo,
                            int* __restrict__ deg, float* __restrict__ stats, int N)
{
    int b = blockIdx.x;
    if (b < 3) {
        const float* W = (b == 0) ? W0 : (b == 1) ? W1 : W2;
        __nv_bfloat16* hi = whi + b * 128 * SA;
        __nv_bfloat16* lo = wlo + b * 128 * SA;
        for (int idx = threadIdx.x; idx < 16384; idx += blockDim.x) {
            int k = idx >> 7, n = idx & 127;     // W[k][n] -> Wt[n][k]
            float w = W[idx];
            __nv_bfloat16 h = __float2bfloat16(w);
            __nv_bfloat16 l = __float2bfloat16(w - __bfloat162float(h));
            hi[n * SA + k] = h;
            lo[n * SA + k] = l;
        }
    } else if (b == 3) {
        // FIX (R9 bug): 4*D = 512 entries but only 256 threads — zero two each.
        stats[threadIdx.x]       = 0.f;
        stats[threadIdx.x + 256] = 0.f;
    } else {
        int per = (N + 11) / 12;
        int beg = (b - 4) * per;
        int end = min(beg + per, N);
        for (int i = beg + (int)threadIdx.x; i < end; i += blockDim.x) deg[i] = 0;
    }
}

// ---------------- HMMA GEMM with fused BN finalize + act ----------------
#define SM_AHI 0
#define SM_ALO 17408
#define SM_WHI 34816
#define SM_WLO 69632
#define SM_BN  104448
#define SM_TOT (104448 + 1024)

__device__ __forceinline__ void mma_bf16(float* c, uint32_t a0, uint32_t a1,
                                         uint32_t a2, uint32_t a3,
                                         uint32_t b0, uint32_t b1)
{
    asm volatile(
        "mma.sync.aligned.m16n8k16.row.col.f32.bf16.bf16.f32 "
        "{%0,%1,%2,%3}, {%4,%5,%6,%7}, {%8,%9}, {%0,%1,%2,%3};"
        : "+f"(c[0]), "+f"(c[1]), "+f"(c[2]), "+f"(c[3])
        : "r"(a0), "r"(a1), "r"(a2), "r"(a3), "r"(b0), "r"(b1));
}

__global__ __launch_bounds__(256) void gemm_mma_kernel(
    const float* __restrict__ H,
    const __nv_bfloat16* __restrict__ whi, const __nv_bfloat16* __restrict__ wlo,
    const float* __restrict__ bias,
    const float* __restrict__ stats,
    const float* __restrict__ gam, const float* __restrict__ bet,
    __half* __restrict__ out, int N, int use_act, float invN)
{
    extern __shared__ char sm[];
    int tid = threadIdx.x, wid = tid >> 5, lane = tid & 31;

    float* sScale = (float*)(sm + SM_BN);
    float* sShift = sScale + 128;

    // fused BN finalize: per-block scale/shift from raw stats
    if (use_act && tid < 128) {
        float m = stats[tid] * invN;
        float v = stats[128 + tid] * invN - m * m;
        float sc = gam[tid] * rsqrtf(v + EPS);
        sScale[tid] = sc;
        sShift[tid] = bet[tid] - m * sc;
    }

    // stage W hi/lo (straight copy, already padded/transposed)
    {
        const float4* bh = (const float4*)whi;
        const float4* bl = (const float4*)wlo;
        float4* sh = (float4*)(sm + SM_WHI);
        float4* sl = (float4*)(sm + SM_WLO);
#pragma unroll
        for (int i = 0; i < 9; i++) {
            int idx = tid + 256 * i;
            if (idx < 2176) { sh[idx] = bh[idx]; sl[idx] = bl[idx]; }
        }
    }
    __syncthreads();   // sScale/sShift ready before A staging

    // stage A tile: load H rows, act, bf16 split, padded store
    int row0 = blockIdx.x * 64;
    {
        const float4* Hv = (const float4*)(H + (size_t)row0 * D);
#pragma unroll
        for (int i = 0; i < 8; i++) {
            int idx = tid + 256 * i;
            int r = idx >> 5;
            int c = (idx & 31) * 4;
            float4 v;
            if (row0 + r < N) v = Hv[idx];
            else              v = make_float4(0.f, 0.f, 0.f, 0.f);
            if (use_act) {
                float4 sc = *(const float4*)(sScale + c);
                float4 sf = *(const float4*)(sShift + c);
                v.x = fmaxf(fmaf(v.x, sc.x, sf.x), 0.f);
                v.y = fmaxf(fmaf(v.y, sc.y, sf.y), 0.f);
                v.z = fmaxf(fmaf(v.z, sc.z, sf.z), 0.f);
                v.w = fmaxf(fmaf(v.w, sc.w, sf.w), 0.f);
            }
            __nv_bfloat162 h01 = __floats2bfloat162_rn(v.x, v.y);
            __nv_bfloat162 h23 = __floats2bfloat162_rn(v.z, v.w);
            float2 hf01 = __bfloat1622float2(h01);
            float2 hf23 = __bfloat1622float2(h23);
            __nv_bfloat162 l01 = __floats2bfloat162_rn(v.x - hf01.x, v.y - hf01.y);
            __nv_bfloat162 l23 = __floats2bfloat162_rn(v.z - hf23.x, v.w - hf23.y);
            uint32_t w0 = (uint32_t)(r * SA_W + (c >> 1));
            uint2 hh; hh.x = *(uint32_t*)&h01; hh.y = *(uint32_t*)&h23;
            uint2 ll; ll.x = *(uint32_t*)&l01; ll.y = *(uint32_t*)&l23;
            *(uint2*)(sm + SM_AHI + w0 * 4) = hh;
            *(uint2*)(sm + SM_ALO + w0 * 4) = ll;
        }
    }
    __syncthreads();

    const uint32_t* pAh = (const uint32_t*)(sm + SM_AHI);
    const uint32_t* pAl = (const uint32_t*)(sm + SM_ALO);
    const uint32_t* pBh = (const uint32_t*)(sm + SM_WHI);
    const uint32_t* pBl = (const uint32_t*)(sm + SM_WLO);

    int m0 = (wid & 3) * 16;
    int n0 = (wid >> 2) * 64;
    int gg = lane >> 2, q = lane & 3;

    float acc[8][4] = {};
#pragma unroll
    for (int k = 0; k < 8; k++) {
        int kb2 = k * 8;
        int ai = (m0 + gg) * SA_W + kb2 + q;
        uint32_t ah0 = pAh[ai],     ah1 = pAh[ai + 8 * SA_W];
        uint32_t ah2 = pAh[ai + 4], ah3 = pAh[ai + 8 * SA_W + 4];
        uint32_t al0 = pAl[ai],     al1 = pAl[ai + 8 * SA_W];
        uint32_t al2 = pAl[ai + 4], al3 = pAl[ai + 8 * SA_W + 4];
#pragma unroll
        for (int t = 0; t < 8; t++) {
            int bi = (n0 + t * 8 + gg) * SA_W + kb2 + q;
            uint32_t bh0 = pBh[bi], bh1 = pBh[bi + 4];
            uint32_t bl0 = pBl[bi], bl1 = pBl[bi + 4];
            mma_bf16(acc[t], ah0, ah1, ah2, ah3, bh0, bh1);
            mma_bf16(acc[t], al0, al1, al2, al3, bh0, bh1);
            mma_bf16(acc[t], ah0, ah1, ah2, ah3, bl0, bl1);
        }
    }

    int r0g = row0 + m0 + gg;
#pragma unroll
    for (int t = 0; t < 8; t++) {
        int colp = n0 + t * 8 + q * 2;
        float2 bv = *(const float2*)(bias + colp);
        if (r0g < N) {
            __half2 o = __floats2half2_rn(acc[t][0] + bv.x, acc[t][1] + bv.y);
            *(__half2*)(out + (size_t)r0g * D + colp) = o;
        }
        if (r0g + 8 < N) {
            __half2 o = __floats2half2_rn(acc[t][2] + bv.x, acc[t][3] + bv.y);
            *(__half2*)(out + (size_t)(r0g + 8) * D + colp) = o;
        }
    }
}

// ---------------- CSR build ----------------
__global__ void hist_kernel(const int* __restrict__ row, int* __restrict__ deg, int E)
{
    int e = blockIdx.x * blockDim.x + threadIdx.x;
    if (e < E) atomicAdd(&deg[row[e]], 1);
}

__global__ __launch_bounds__(1024) void blocksum_kernel(
    const int* __restrict__ deg, int* __restrict__ blksum, int N)
{
    int i = blockIdx.x * 1024 + threadIdx.x;
    int v = (i < N) ? deg[i] : 0;
#pragma unroll
    for (int off = 16; off > 0; off >>= 1) v += __shfl_down_sync(0xffffffffu, v, off);
    __shared__ int smr[32];
    int lane = threadIdx.x & 31, wid = threadIdx.x >> 5;
    if (lane == 0) smr[wid] = v;
    __syncthreads();
    if (wid == 0) {
        v = smr[lane];
#pragma unroll
        for (int off = 16; off > 0; off >>= 1) v += __shfl_down_sync(0xffffffffu, v, off);
        if (lane == 0) blksum[blockIdx.x] = v;
    }
}

__global__ __launch_bounds__(1024) void scanpart_kernel(int* __restrict__ blksum, int nb)
{
    __shared__ int smr[1024];
    int tid = threadIdx.x;
    smr[tid] = (tid < nb) ? blksum[tid] : 0;
    __syncthreads();
    if (tid == 0) {
        int run = 0;
        for (int i = 0; i < nb; i++) { int t = smr[i]; smr[i] = run; run += t; }
    }
    __syncthreads();
    if (tid < nb) blksum[tid] = smr[tid];
}

__global__ __launch_bounds__(1024) void rowptr_kernel(
    const int* __restrict__ deg, const int* __restrict__ blksum,
    int* __restrict__ rowptr, int* __restrict__ cursor, int N)
{
    int i = blockIdx.x * 1024 + threadIdx.x;
    int v = (i < N) ? deg[i] : 0;
    int lane = threadIdx.x & 31, wid = threadIdx.x >> 5;
    int incl = v;
#pragma unroll
    for (int off = 1; off < 32; off <<= 1) {
        int t = __shfl_up_sync(0xffffffffu, incl, off);
        if (lane >= off) incl += t;
    }
    __shared__ int wsum[32];
    if (lane == 31) wsum[wid] = incl;
    __syncthreads();
    if (wid == 0) {
        int w = wsum[lane];
#pragma unroll
        for (int off = 1; off < 32; off <<= 1) {
            int t = __shfl_up_sync(0xffffffffu, w, off);
            if (lane >= off) w += t;
        }
        wsum[lane] = w;
    }
    __syncthreads();
    int offset = blksum[blockIdx.x] + (wid > 0 ? wsum[wid - 1] : 0);
    int excl = offset + incl - v;
    if (i < N) { rowptr[i] = excl; cursor[i] = excl; }
    if (i == N - 1) rowptr[N] = excl + v;
}

__global__ void scatter_kernel(
    const int* __restrict__ row, const int* __restrict__ col,
    const float* __restrict__ ew, int* __restrict__ cursor,
    int2* __restrict__ edata, int E)
{
    int e = blockIdx.x * blockDim.x + threadIdx.x;
    if (e < E) {
        int p = atomicAdd(&cursor[row[e]], 1);
        int2 ed; ed.x = col[e]; ed.y = __float_as_int(ew[e]);
        edata[p] = ed;
    }
}

// ---------------- gather SpMM (fp16 in, fp32 out): one warp per row ----------------
__global__ __launch_bounds__(256) void spmm_kernel(
    const __half* __restrict__ H, const int* __restrict__ rowptr,
    const int2* __restrict__ edata, float* __restrict__ out, int N)
{
    int r = blockIdx.x * 8 + (threadIdx.x >> 5);
    if (r >= N) return;
    int lane = threadIdx.x & 31;
    int start = rowptr[r], end = rowptr[r + 1];

    float4 acc = make_float4(0.f, 0.f, 0.f, 0.f);
    const uint2* Hv = (const uint2*)H;

    for (int base = start; base < end; base += 32) {
        int e = base + lane;
        int c = 0, wb = 0;
        if (e < end) { int2 ed = edata[e]; c = ed.x; wb = ed.y; }
        int cnt = min(32, end - base);
#pragma unroll 4
        for (int i = 0; i < cnt; i++) {
            int ci = __shfl_sync(0xffffffffu, c, i);
            float wi = __int_as_float(__shfl_sync(0xffffffffu, wb, i));
            uint2 pv = Hv[(size_t)ci * 32 + lane];
            float2 v01 = __half22float2(*(__half2*)&pv.x);
            float2 v23 = __half22float2(*(__half2*)&pv.y);
            acc.x = fmaf(wi, v01.x, acc.x);
            acc.y = fmaf(wi, v01.y, acc.y);
            acc.z = fmaf(wi, v23.x, acc.z);
            acc.w = fmaf(wi, v23.y, acc.w);
        }
    }
    ((float4*)(out + (size_t)r * D))[lane] = acc;
}

// ---------------- BN stats (reads L2-resident A) ----------------
#define RPB 256
__global__ __launch_bounds__(128) void bn_stats_kernel(
    const float* __restrict__ A, float* __restrict__ stats, int N)
{
    int d = threadIdx.x;
    int r0 = blockIdx.x * RPB;
    int rend = min(r0 + RPB, N);
    float s = 0.f, q = 0.f;
    for (int r = r0; r < rend; r++) {
        float v = A[(size_t)r * D + d];
        s += v;
        q = fmaf(v, v, q);
    }
    atomicAdd(&stats[d], s);
    atomicAdd(&stats[128 + d], q);
}

// ---------------------------------------------------------------------------
extern "C" void kernel_launch(void* const* d_in, const int* in_sizes, int n_in,
                              void* d_out, int out_size)
{
    const float* x   = (const float*)d_in[0];
    const float* ew  = (const float*)d_in[1];
    const float* W0  = (const float*)d_in[2];
    const float* b0  = (const float*)d_in[3];
    const float* g0  = (const float*)d_in[4];
    const float* be0 = (const float*)d_in[5];
    const float* W1  = (const float*)d_in[6];
    const float* b1  = (const float*)d_in[7];
    const float* g1  = (const float*)d_in[8];
    const float* be1 = (const float*)d_in[9];
    const float* W2  = (const float*)d_in[10];
    const float* b2  = (const float*)d_in[11];
    const int*   row = (const int*)d_in[12];
    const int*   col = (const int*)d_in[13];
    float* out = (float*)d_out;

    int N = in_sizes[0] / D;
    int E = in_sizes[1];

    float *A, *Stats;
    __half* Z;
    int *Deg, *Rowptr, *Cursor, *Blksum;
    int2* Edata;
    __nv_bfloat16 *Whi, *Wlo;
    cudaGetSymbolAddress((void**)&Z, g_Z);
    cudaGetSymbolAddress((void**)&A, g_A);
    cudaGetSymbolAddress((void**)&Stats, g_stats);
    cudaGetSymbolAddress((void**)&Deg, g_deg);
    cudaGetSymbolAddress((void**)&Rowptr, g_rowptr);
    cudaGetSymbolAddress((void**)&Cursor, g_cursor);
    cudaGetSymbolAddress((void**)&Edata, g_edata);
    cudaGetSymbolAddress((void**)&Blksum, g_blksum);
    cudaGetSymbolAddress((void**)&Whi, g_Whi);
    cudaGetSymbolAddress((void**)&Wlo, g_Wlo);

    cudaFuncSetAttribute(gemm_mma_kernel, cudaFuncAttributeMaxDynamicSharedMemorySize, SM_TOT);

    int gemmGrid  = (N + 63) / 64;
    int spmmGrid  = (N + 7) / 8;
    int statsGrid = (N + RPB - 1) / RPB;
    int nb        = (N + 1023) / 1024;
    float invN = 1.0f / (float)N;

    // ---- prep + CSR build (single stream, capture-safe) ----
    prep_kernel<<<16, 256>>>(W0, W1, W2, Whi, Wlo, Deg, Stats, N);
    hist_kernel<<<(E + 255) / 256, 256>>>(row, Deg, E);
    blocksum_kernel<<<nb, 1024>>>(Deg, Blksum, N);
    scanpart_kernel<<<1, 1024>>>(Blksum, nb);
    rowptr_kernel<<<nb, 1024>>>(Deg, Blksum, Rowptr, Cursor, N);
    scatter_kernel<<<(E + 255) / 256, 256>>>(row, col, ew, Cursor, Edata, E);

    // ---- layer 0 ----
    gemm_mma_kernel<<<gemmGrid, 256, SM_TOT>>>(x, Whi, Wlo, b0, nullptr, nullptr, nullptr,
                                               Z, N, 0, invN);
    spmm_kernel<<<spmmGrid, 256>>>(Z, Rowptr, Edata, A, N);
    bn_stats_kernel<<<statsGrid, 128>>>(A, Stats, N);

    // ---- layer 1 (applies BN0 fused) ----
    gemm_mma_kernel<<<gemmGrid, 256, SM_TOT>>>(A, Whi + 128 * SA, Wlo + 128 * SA, b1,
                                               Stats, g0, be0, Z, N, 1, invN);
    spmm_kernel<<<spmmGrid, 256>>>(Z, Rowptr, Edata, A, N);
    bn_stats_kernel<<<statsGrid, 128>>>(A, Stats + 256, N);

    // ---- layer 2 (applies BN1 fused) ----
    gemm_mma_kernel<<<gemmGrid, 256, SM_TOT>>>(A, Whi + 256 * SA, Wlo + 256 * SA, b2,
                                               Stats + 256, g1, be1, Z, N, 1, invN);
    spmm_kernel<<<spmmGrid, 256>>>(Z, Rowptr, Edata, out, N);
}